// round 13
// baseline (speedup 1.0000x reference)
#include <cuda_runtime.h>
#include <cuda_fp16.h>
#include <cstdint>

// ---------------- problem constants ----------------
#define Bn    32
#define Wd    56
#define Cc    128
// SCALE * log2(e): logits in log2 domain -> ex2
#define SCALE_L2E (0.17677669529663687f * 1.4426950408889634f)

// M=64 (49 q), N=256 (245 k), K=32. fp16 operands, fp32 accum.
// 512 threads, 16 warps: warp = (mt = w&3) x (kq = w>>2); kq owns 64 keys.
// Online softmax (per-kq local max, epilogue rescale), 2 barriers.
// ---------------- smem layout (word offsets) ----------------
#define OFF_Q    0          // 64 x 40 halves   = 1280 words
#define OFF_K    1280       // 256 x 40 halves  = 5120
#define OFF_V    6400       // 256 x 40 halves  = 5120
#define OFF_RMP  11520      // 64 rows x 4 local maxes
#define OFF_RSP  11776      // 64 rows x 4 local sums
#define OFF_RED  12032      // 3 kq x 4 mt x 2 x 128 words (fp16 partials) = 3072
#define OFF_LEP  15104      // 49 x 32 fp32 = 1568
#define OFF_VC   16672      // 49 x 32 fp32 center-V tile = 1568
#define OFF_WL   18240      // 9 taps x 32 ch fp32 = 288
#define OFF_WLB  18528      // 32 ch fp32 bias
#define SMEM_WORDS 18560
#define SMEM_BYTES (SMEM_WORDS * 4)   // 74,240 B -> 2 CTAs/SM

__device__ __forceinline__ void ldsm_x4(unsigned r[4], const void* p) {
    unsigned a = (unsigned)__cvta_generic_to_shared(p);
    asm volatile("ldmatrix.sync.aligned.m8n8.x4.shared.b16 {%0,%1,%2,%3}, [%4];"
        : "=r"(r[0]), "=r"(r[1]), "=r"(r[2]), "=r"(r[3]) : "r"(a));
}
__device__ __forceinline__ void ldsm_x4t(unsigned r[4], const void* p) {
    unsigned a = (unsigned)__cvta_generic_to_shared(p);
    asm volatile("ldmatrix.sync.aligned.m8n8.x4.trans.shared.b16 {%0,%1,%2,%3}, [%4];"
        : "=r"(r[0]), "=r"(r[1]), "=r"(r[2]), "=r"(r[3]) : "r"(a));
}
__device__ __forceinline__ void mma_f16(float c[4],
                                        unsigned a0, unsigned a1, unsigned a2, unsigned a3,
                                        unsigned b0, unsigned b1) {
    asm volatile(
        "mma.sync.aligned.m16n8k16.row.col.f32.f16.f16.f32 "
        "{%0,%1,%2,%3}, {%4,%5,%6,%7}, {%8,%9}, {%0,%1,%2,%3};"
        : "+f"(c[0]), "+f"(c[1]), "+f"(c[2]), "+f"(c[3])
        : "r"(a0), "r"(a1), "r"(a2), "r"(a3), "r"(b0), "r"(b1));
}
__device__ __forceinline__ unsigned pack_h2(float a, float b) {
    __half2 h = __floats2half2_rn(a, b);
    return *(unsigned*)&h;
}
__device__ __forceinline__ float ex2(float x) {
    float y;
    asm("ex2.approx.ftz.f32 %0, %1;" : "=f"(y) : "f"(x));
    return y;
}

__global__ __launch_bounds__(512, 2)
void lepe_attn_kernel(const float* __restrict__ qkv,
                      const float* __restrict__ w_lepe,
                      const float* __restrict__ b_lepe,
                      float* __restrict__ out)
{
    extern __shared__ float smf[];
    __half* smh = (__half*)smf;

    const int bid = blockIdx.x;
    const int h   = bid & 3;
    const int pw  = (bid >> 2) & 7;
    const int ph  = (bid >> 5) & 7;
    const int b   = bid >> 8;
    const int tid = threadIdx.x;
    const int w   = tid >> 5;
    const int lane = tid & 31;
    const int g   = lane >> 2;
    const int t   = lane & 3;
    const int mt  = w & 3;
    const int kq  = w >> 2;

    const size_t plane = (size_t)Wd * Wd * Cc;
    const float* qg = qkv + (size_t)b * plane;
    const float* kg = qkv + (size_t)Bn * plane     + (size_t)b * plane;
    const float* vg = qkv + (size_t)2 * Bn * plane + (size_t)b * plane;
    const int cbase = h * 32;

    // ================= load phase =================
    __half* Qh = smh + OFF_Q * 2;
    __half* Kh = smh + OFF_K * 2;
    __half* Vh = smh + OFF_V * 2;
    {   // Q: one float4 per thread; lanes 0-7 cover one full row line
        int r  = tid >> 3;
        int dv = (tid & 7) << 2;
        __half2 h01 = __floats2half2_rn(0.f, 0.f), h23 = h01;
        if (r < 49) {
            int qi = r / 7, qj = r - 7 * (r / 7);
            int pix = (ph * 7 + qi) * Wd + pw * 7 + qj;
            float4 v = *(const float4*)(qg + (size_t)pix * Cc + cbase + dv);
            h01 = __floats2half2_rn(v.x * SCALE_L2E, v.y * SCALE_L2E);
            h23 = __floats2half2_rn(v.z * SCALE_L2E, v.w * SCALE_L2E);
        }
        *(uint2*)(Qh + r * 40 + dv) = make_uint2(*(unsigned*)&h01, *(unsigned*)&h23);
    }
    // lepe weights for this head -> smem (covered by barrier 1)
    if (tid < 288) smf[OFF_WL + tid] = w_lepe[(tid >> 5) * Cc + cbase + (tid & 31)];
    else if (tid >= 480) smf[OFF_WLB + tid - 480] = b_lepe[cbase + tid - 480];

    // K/V: 16B per thread per array; lanes 0-7 cover one full 128B row line.
    // Center-V columns (kx in [14,21)) additionally staged as fp32 -> VC.
    #pragma unroll
    for (int it = 0; it < 4; it++) {
        int idx = tid + it * 512;
        int kk = idx >> 3;
        int dv = (idx & 7) << 2;
        float4 kv = make_float4(0.f, 0.f, 0.f, 0.f);
        float4 vv = make_float4(0.f, 0.f, 0.f, 0.f);
        if (kk < 245) {
            int ky = kk / 35, kx = kk - 35 * (kk / 35);
            int x = pw * 7 + kx - 14;
            int y = ph * 7 + ky;
            if (x >= 0 && x < Wd) {
                size_t gi = (size_t)(y * Wd + x) * Cc + cbase + dv;
                kv = *(const float4*)(kg + gi);
                vv = *(const float4*)(vg + gi);
            }
            if (kx >= 14 && kx < 21)
                *(float4*)(smf + OFF_VC + (ky * 7 + kx - 14) * 32 + dv) = vv;
        }
        *(uint2*)(Kh + kk * 40 + dv) = make_uint2(pack_h2(kv.x, kv.y), pack_h2(kv.z, kv.w));
        *(uint2*)(Vh + kk * 40 + dv) = make_uint2(pack_h2(vv.x, vv.y), pack_h2(vv.z, vv.w));
    }
    __syncthreads();   // (1)

    // ================= QK^T: warp = (mt, kq), 16 HMMA =================
    const int arow = lane & 15, acol = (lane >> 4) << 3;
    const int brow = (lane & 7) + ((lane >> 4) << 3);
    const int bcol = ((lane >> 3) & 1) << 3;
    unsigned aq[2][4];
    ldsm_x4(aq[0], Qh + (mt * 16 + arow) * 40 + acol);
    ldsm_x4(aq[1], Qh + (mt * 16 + arow) * 40 + 16 + acol);

    // acc init: -20000 on pad columns (>=245); MMA adds zero-K contributions,
    // so pads stay huge-negative and ex2 underflows them to exact 0.
    float acc[8][4];
    #pragma unroll
    for (int nt = 0; nt < 8; nt++) {
        int c0 = kq * 64 + nt * 8 + 2 * t;
        float i0 = (c0     < 245) ? 0.f : -20000.f;
        float i1 = (c0 + 1 < 245) ? 0.f : -20000.f;
        acc[nt][0] = i0; acc[nt][1] = i1; acc[nt][2] = i0; acc[nt][3] = i1;
    }

    #pragma unroll
    for (int j = 0; j < 4; j++) {
        int n0 = kq * 64 + j * 16;
        #pragma unroll
        for (int ks = 0; ks < 2; ks++) {
            unsigned bk[4];
            ldsm_x4(bk, Kh + (n0 + brow) * 40 + ks * 16 + bcol);
            mma_f16(acc[2 * j],     aq[ks][0], aq[ks][1], aq[ks][2], aq[ks][3], bk[0], bk[1]);
            mma_f16(acc[2 * j + 1], aq[ks][0], aq[ks][1], aq[ks][2], aq[ks][3], bk[2], bk[3]);
        }
    }

    // ---- LePE conv: lane = channel, fp32 VC tile, 1-wf accesses ----
    #pragma unroll
    for (int rr = 0; rr < 4; rr++) {
        int r = (rr == 3) ? 48 : (w + rr * 16);
        if (rr < 3 || w == 0) {
            int qi = r / 7, qj = r - 7 * (r / 7);
            float l = smf[OFF_WLB + lane];
            #pragma unroll
            for (int tap = 0; tap < 9; tap++) {
                int yy = qi + tap / 3 - 1;
                int xx = qj + tap - 3 * (tap / 3) - 1;
                if (yy >= 0 && yy < 7 && xx >= 0 && xx < 7)
                    l = fmaf(smf[OFF_WL + tap * 32 + lane],
                             smf[OFF_VC + (yy * 7 + xx) * 32 + lane], l);
            }
            smf[OFF_LEP + r * 32 + lane] = l;
        }
    }

    // ================= local softmax (per-kq max; exact after rescale) =====
    const int r0 = mt * 16 + g, r1 = r0 + 8;
    float m0 = -1e30f, m1 = -1e30f;
    #pragma unroll
    for (int nt = 0; nt < 8; nt++) {
        m0 = fmaxf(m0, fmaxf(acc[nt][0], acc[nt][1]));
        m1 = fmaxf(m1, fmaxf(acc[nt][2], acc[nt][3]));
    }
    #pragma unroll
    for (int s = 1; s <= 2; s <<= 1) {
        m0 = fmaxf(m0, __shfl_xor_sync(0xffffffffu, m0, s));
        m1 = fmaxf(m1, __shfl_xor_sync(0xffffffffu, m1, s));
    }

    unsigned ah[8], bh[8];
    float s0 = 0.f, s1 = 0.f;
    #pragma unroll
    for (int nt = 0; nt < 8; nt++) {
        float e0 = ex2(acc[nt][0] - m0);
        float e1 = ex2(acc[nt][1] - m0);
        float e2 = ex2(acc[nt][2] - m1);
        float e3 = ex2(acc[nt][3] - m1);
        s0 += e0 + e1; s1 += e2 + e3;
        ah[nt] = pack_h2(e0, e1);
        bh[nt] = pack_h2(e2, e3);
    }
    #pragma unroll
    for (int s = 1; s <= 2; s <<= 1) {
        s0 += __shfl_xor_sync(0xffffffffu, s0, s);
        s1 += __shfl_xor_sync(0xffffffffu, s1, s);
    }
    if (t == 0) {
        smf[OFF_RMP + r0 * 4 + kq] = m0;
        smf[OFF_RMP + r1 * 4 + kq] = m1;
        smf[OFF_RSP + r0 * 4 + kq] = s0;
        smf[OFF_RSP + r1 * 4 + kq] = s1;
    }

    // ================= P @ V: A regs, B = ldsm.trans(V) =================
    const int vky  = (lane & 7) + (((lane >> 3) & 1) << 3);
    const int vdim = (lane >> 4) << 3;
    float pa[4][4];
    #pragma unroll
    for (int nt = 0; nt < 4; nt++)
        #pragma unroll
        for (int e = 0; e < 4; e++) pa[nt][e] = 0.f;

    #pragma unroll
    for (int ks = 0; ks < 4; ks++) {
        const __half* vp = Vh + (kq * 64 + ks * 16 + vky) * 40;
        unsigned bv0[4], bv1[4];
        ldsm_x4t(bv0, vp + vdim);
        ldsm_x4t(bv1, vp + 16 + vdim);
        unsigned a0 = ah[2 * ks], a1 = bh[2 * ks], a2 = ah[2 * ks + 1], a3 = bh[2 * ks + 1];
        mma_f16(pa[0], a0, a1, a2, a3, bv0[0], bv0[1]);
        mma_f16(pa[1], a0, a1, a2, a3, bv0[2], bv0[3]);
        mma_f16(pa[2], a0, a1, a2, a3, bv1[0], bv1[1]);
        mma_f16(pa[3], a0, a1, a2, a3, bv1[2], bv1[3]);
    }

    // kq 1..3 store fp16 partials (relative to their local max)
    if (kq > 0) {
        uint4* red = (uint4*)(smf + OFF_RED) + ((kq - 1) * 4 + mt) * 64;
        red[lane]      = make_uint4(pack_h2(pa[0][0], pa[0][1]), pack_h2(pa[1][0], pa[1][1]),
                                    pack_h2(pa[2][0], pa[2][1]), pack_h2(pa[3][0], pa[3][1]));
        red[32 + lane] = make_uint4(pack_h2(pa[0][2], pa[0][3]), pack_h2(pa[1][2], pa[1][3]),
                                    pack_h2(pa[2][2], pa[2][3]), pack_h2(pa[3][2], pa[3][3]));
    }
    __syncthreads();   // (2) RED + RMP + RSP + LEP ready

    // ================= epilogue (kq == 0): rescale-combine =================
    if (kq == 0) {
        float4 mv0 = *(const float4*)(smf + OFF_RMP + r0 * 4);
        float4 mv1 = *(const float4*)(smf + OFF_RMP + r1 * 4);
        float4 sv0 = *(const float4*)(smf + OFF_RSP + r0 * 4);
        float4 sv1 = *(const float4*)(smf + OFF_RSP + r1 * 4);
        float mg0 = fmaxf(fmaxf(mv0.x, mv0.y), fmaxf(mv0.z, mv0.w));
        float mg1 = fmaxf(fmaxf(mv1.x, mv1.y), fmaxf(mv1.z, mv1.w));
        float c00 = ex2(mv0.x - mg0), c01 = ex2(mv0.y - mg0);
        float c02 = ex2(mv0.z - mg0), c03 = ex2(mv0.w - mg0);
        float c10 = ex2(mv1.x - mg1), c11 = ex2(mv1.y - mg1);
        float c12 = ex2(mv1.z - mg1), c13 = ex2(mv1.w - mg1);
        float den0 = sv0.x * c00 + sv0.y * c01 + sv0.z * c02 + sv0.w * c03;
        float den1 = sv1.x * c10 + sv1.y * c11 + sv1.z * c12 + sv1.w * c13;

        #pragma unroll
        for (int nt = 0; nt < 4; nt++) {
            pa[nt][0] *= c00; pa[nt][1] *= c00;
            pa[nt][2] *= c10; pa[nt][3] *= c10;
        }
        float sc0[3] = {c01, c02, c03};
        float sc1[3] = {c11, c12, c13};
        #pragma unroll
        for (int q = 0; q < 3; q++) {
            const uint4* red = (const uint4*)(smf + OFF_RED) + (q * 4 + mt) * 64;
            uint4 u0 = red[lane];
            uint4 u1 = red[32 + lane];
            const unsigned* p0 = (const unsigned*)&u0;
            const unsigned* p1 = (const unsigned*)&u1;
            #pragma unroll
            for (int nt = 0; nt < 4; nt++) {
                float2 f0 = __half22float2(*(const __half2*)&p0[nt]);
                float2 f1 = __half22float2(*(const __half2*)&p1[nt]);
                pa[nt][0] = fmaf(f0.x, sc0[q], pa[nt][0]);
                pa[nt][1] = fmaf(f0.y, sc0[q], pa[nt][1]);
                pa[nt][2] = fmaf(f1.x, sc1[q], pa[nt][2]);
                pa[nt][3] = fmaf(f1.y, sc1[q], pa[nt][3]);
            }
        }
        float inv0 = 1.0f / den0;
        float inv1 = 1.0f / den1;

        #pragma unroll
        for (int half = 0; half < 2; half++) {
            int row = half ? r1 : r0;
            if (row >= 49) continue;
            float inv = half ? inv1 : inv0;
            int qi = row / 7, qj = row - 7 * (row / 7);
            int pix = (ph * 7 + qi) * Wd + pw * 7 + qj;
            float* op = out + (size_t)b * plane + (size_t)pix * Cc + cbase;
            #pragma unroll
            for (int nt = 0; nt < 4; nt++) {
                int d0 = nt * 8 + 2 * t;
                float2 lep = *(const float2*)(smf + OFF_LEP + row * 32 + d0);
                float o0 = pa[nt][half * 2 + 0] * inv + lep.x;
                float o1 = pa[nt][half * 2 + 1] * inv + lep.y;
                *(float2*)(op + d0) = make_float2(o0, o1);
            }
        }
    }
}

extern "C" void kernel_launch(void* const* d_in, const int* in_sizes, int n_in,
                              void* d_out, int out_size)
{
    const float* qkv    = (const float*)d_in[0];
    const float* w_lepe = (const float*)d_in[1];
    const float* b_lepe = (const float*)d_in[2];
    float* out          = (float*)d_out;

    cudaFuncSetAttribute(lepe_attn_kernel,
                         cudaFuncAttributeMaxDynamicSharedMemorySize, SMEM_BYTES);
    lepe_attn_kernel<<<Bn * 8 * 8 * 4, 512, SMEM_BYTES>>>(qkv, w_lepe, b_lepe, out);
}

// round 14
// speedup vs baseline: 1.0984x; 1.0984x over previous
#include <cuda_runtime.h>
#include <cuda_fp16.h>
#include <cstdint>

// ---------------- problem constants ----------------
#define Bn    32
#define Wd    56
#define Cc    128
// SCALE * log2(e): logits in log2 domain -> ex2
#define SCALE_L2E (0.17677669529663687f * 1.4426950408889634f)

// M=64 (49 q), N=256 (245 k), K=32. fp16 operands, fp32 accum.
// 512 threads, 16 warps: warp = (mt = w&3) x (kq = w>>2); kq owns 64 keys.
// Online softmax: per-kq local max, epilogue rescale. 2 barriers total.
// ---------------- smem layout (word offsets) ----------------
#define OFF_Q    0          // 64 x 40 halves   = 1280 words
#define OFF_K    1280       // 256 x 40 halves  = 5120
#define OFF_V    6400       // 256 x 40 halves  = 5120
#define OFF_RMP  11520      // 64 rows x 4 local maxes
#define OFF_RSP  11776      // 64 rows x 4 local sums
#define OFF_RED  12032      // 3 kq x 4 mt x 2 x 128 words (fp16 partials) = 3072
#define OFF_LEP  15104      // 49 x 32 fp32 = 1568
#define OFF_WL   16672      // 9 taps x 32 ch fp32 = 288 (this head's lepe weights)
#define OFF_WLB  16960      // 32 ch fp32 bias
#define SMEM_WORDS 16992
#define SMEM_BYTES (SMEM_WORDS * 4)   // 67,968 B -> 2 CTAs/SM

__device__ __forceinline__ void ldsm_x4(unsigned r[4], const void* p) {
    unsigned a = (unsigned)__cvta_generic_to_shared(p);
    asm volatile("ldmatrix.sync.aligned.m8n8.x4.shared.b16 {%0,%1,%2,%3}, [%4];"
        : "=r"(r[0]), "=r"(r[1]), "=r"(r[2]), "=r"(r[3]) : "r"(a));
}
__device__ __forceinline__ void ldsm_x4t(unsigned r[4], const void* p) {
    unsigned a = (unsigned)__cvta_generic_to_shared(p);
    asm volatile("ldmatrix.sync.aligned.m8n8.x4.trans.shared.b16 {%0,%1,%2,%3}, [%4];"
        : "=r"(r[0]), "=r"(r[1]), "=r"(r[2]), "=r"(r[3]) : "r"(a));
}
__device__ __forceinline__ void mma_f16(float c[4],
                                        unsigned a0, unsigned a1, unsigned a2, unsigned a3,
                                        unsigned b0, unsigned b1) {
    asm volatile(
        "mma.sync.aligned.m16n8k16.row.col.f32.f16.f16.f32 "
        "{%0,%1,%2,%3}, {%4,%5,%6,%7}, {%8,%9}, {%0,%1,%2,%3};"
        : "+f"(c[0]), "+f"(c[1]), "+f"(c[2]), "+f"(c[3])
        : "r"(a0), "r"(a1), "r"(a2), "r"(a3), "r"(b0), "r"(b1));
}
__device__ __forceinline__ unsigned pack_h2(float a, float b) {
    __half2 h = __floats2half2_rn(a, b);
    return *(unsigned*)&h;
}
__device__ __forceinline__ float ex2(float x) {
    float y;
    asm("ex2.approx.ftz.f32 %0, %1;" : "=f"(y) : "f"(x));
    return y;
}

__global__ __launch_bounds__(512, 2)
void lepe_attn_kernel(const float* __restrict__ qkv,
                      const float* __restrict__ w_lepe,
                      const float* __restrict__ b_lepe,
                      float* __restrict__ out)
{
    extern __shared__ float smf[];
    __half* smh = (__half*)smf;

    const int bid = blockIdx.x;
    const int h   = bid & 3;
    const int pw  = (bid >> 2) & 7;
    const int ph  = (bid >> 5) & 7;
    const int b   = bid >> 8;
    const int tid = threadIdx.x;
    const int w   = tid >> 5;
    const int lane = tid & 31;
    const int g   = lane >> 2;
    const int t   = lane & 3;
    const int mt  = w & 3;
    const int kq  = w >> 2;

    const size_t plane = (size_t)Wd * Wd * Cc;
    const float* qg = qkv + (size_t)b * plane;
    const float* kg = qkv + (size_t)Bn * plane     + (size_t)b * plane;
    const float* vg = qkv + (size_t)2 * Bn * plane + (size_t)b * plane;
    const int cbase = h * 32;

    // ================= load phase =================
    __half* Qh = smh + OFF_Q * 2;
    __half* Kh = smh + OFF_K * 2;
    __half* Vh = smh + OFF_V * 2;
    {   // Q: one float4 per thread (64 rows x 8 chunks); lanes 0-7 = one row line
        int r  = tid >> 3;
        int dv = (tid & 7) << 2;
        __half2 h01 = __floats2half2_rn(0.f, 0.f), h23 = h01;
        if (r < 49) {
            int qi = r / 7, qj = r - 7 * (r / 7);
            int pix = (ph * 7 + qi) * Wd + pw * 7 + qj;
            float4 v = *(const float4*)(qg + (size_t)pix * Cc + cbase + dv);
            h01 = __floats2half2_rn(v.x * SCALE_L2E, v.y * SCALE_L2E);
            h23 = __floats2half2_rn(v.z * SCALE_L2E, v.w * SCALE_L2E);
        }
        *(uint2*)(Qh + r * 40 + dv) = make_uint2(*(unsigned*)&h01, *(unsigned*)&h23);
    }
    // lepe weights for this head -> smem (covered by barrier 1)
    if (tid < 288) smf[OFF_WL + tid] = w_lepe[(tid >> 5) * Cc + cbase + (tid & 31)];
    else if (tid >= 480) smf[OFF_WLB + tid - 480] = b_lepe[cbase + tid - 480];

    // K/V: 16B per thread per array; lanes 0-7 cover one full 128B row line.
    #pragma unroll
    for (int it = 0; it < 4; it++) {
        int idx = tid + it * 512;
        int kk = idx >> 3;
        int dv = (idx & 7) << 2;
        float4 kv = make_float4(0.f, 0.f, 0.f, 0.f);
        float4 vv = make_float4(0.f, 0.f, 0.f, 0.f);
        if (kk < 245) {
            int ky = kk / 35, kx = kk - 35 * (kk / 35);
            int x = pw * 7 + kx - 14;
            int y = ph * 7 + ky;
            if (x >= 0 && x < Wd) {
                size_t gi = (size_t)(y * Wd + x) * Cc + cbase + dv;
                kv = *(const float4*)(kg + gi);
                vv = *(const float4*)(vg + gi);
            }
        }
        *(uint2*)(Kh + kk * 40 + dv) = make_uint2(pack_h2(kv.x, kv.y), pack_h2(kv.z, kv.w));
        *(uint2*)(Vh + kk * 40 + dv) = make_uint2(pack_h2(vv.x, vv.y), pack_h2(vv.z, vv.w));
    }
    __syncthreads();   // (1)

    // ================= QK^T: warp = (mt, kq), 16 HMMA =================
    const int arow = lane & 15, acol = (lane >> 4) << 3;
    const int brow = (lane & 7) + ((lane >> 4) << 3);
    const int bcol = ((lane >> 3) & 1) << 3;
    unsigned aq[2][4];
    ldsm_x4(aq[0], Qh + (mt * 16 + arow) * 40 + acol);
    ldsm_x4(aq[1], Qh + (mt * 16 + arow) * 40 + 16 + acol);

    // acc init: -20000 on pad columns (>=245). K pad rows are zero in smem, so
    // the MMA adds 0 there and ex2 underflows pads to exact 0 — no predicates.
    float acc[8][4];
    #pragma unroll
    for (int nt = 0; nt < 8; nt++) {
        int c0 = kq * 64 + nt * 8 + 2 * t;
        float i0 = (c0     < 245) ? 0.f : -20000.f;
        float i1 = (c0 + 1 < 245) ? 0.f : -20000.f;
        acc[nt][0] = i0; acc[nt][1] = i1; acc[nt][2] = i0; acc[nt][3] = i1;
    }

    #pragma unroll
    for (int j = 0; j < 4; j++) {
        int n0 = kq * 64 + j * 16;
        #pragma unroll
        for (int ks = 0; ks < 2; ks++) {
            unsigned bk[4];
            ldsm_x4(bk, Kh + (n0 + brow) * 40 + ks * 16 + bcol);
            mma_f16(acc[2 * j],     aq[ks][0], aq[ks][1], aq[ks][2], aq[ks][3], bk[0], bk[1]);
            mma_f16(acc[2 * j + 1], aq[ks][0], aq[ks][1], aq[ks][2], aq[ks][3], bk[2], bk[3]);
        }
    }

    // ---- LePE conv from smem weights + Vh (independent; fills HMMA drain) ----
    for (int idx = tid; idx < 49 * 16; idx += 512) {
        int row = idx >> 4, dp = idx & 15;
        int qi = row / 7, qj = row - 7 * (row / 7);
        float2 bl = *(const float2*)(smf + OFF_WLB + 2 * dp);
        float l0 = bl.x, l1 = bl.y;
        #pragma unroll
        for (int di = -1; di <= 1; di++) {
            int yy = qi + di;
            if (yy < 0 || yy >= 7) continue;
            #pragma unroll
            for (int dj = -1; dj <= 1; dj++) {
                int xx = qj + dj;
                if (xx < 0 || xx >= 7) continue;
                int key = yy * 35 + 14 + xx;
                float2 wv = *(const float2*)(smf + OFF_WL + ((di + 1) * 3 + dj + 1) * 32 + 2 * dp);
                float2 vf = __half22float2(*(const __half2*)(Vh + key * 40 + 2 * dp));
                l0 = fmaf(wv.x, vf.x, l0);
                l1 = fmaf(wv.y, vf.y, l1);
            }
        }
        *(float2*)(smf + OFF_LEP + row * 32 + 2 * dp) = make_float2(l0, l1);
    }

    // ================= local softmax (per-kq max; exact after rescale) =====
    const int r0 = mt * 16 + g, r1 = r0 + 8;
    float m0 = -1e30f, m1 = -1e30f;
    #pragma unroll
    for (int nt = 0; nt < 8; nt++) {
        m0 = fmaxf(m0, fmaxf(acc[nt][0], acc[nt][1]));
        m1 = fmaxf(m1, fmaxf(acc[nt][2], acc[nt][3]));
    }
    #pragma unroll
    for (int s = 1; s <= 2; s <<= 1) {
        m0 = fmaxf(m0, __shfl_xor_sync(0xffffffffu, m0, s));
        m1 = fmaxf(m1, __shfl_xor_sync(0xffffffffu, m1, s));
    }

    unsigned ah[8], bh[8];
    float s0 = 0.f, s1 = 0.f;
    #pragma unroll
    for (int nt = 0; nt < 8; nt++) {
        float e0 = ex2(acc[nt][0] - m0);
        float e1 = ex2(acc[nt][1] - m0);
        float e2 = ex2(acc[nt][2] - m1);
        float e3 = ex2(acc[nt][3] - m1);
        s0 += e0 + e1; s1 += e2 + e3;
        ah[nt] = pack_h2(e0, e1);
        bh[nt] = pack_h2(e2, e3);
    }
    #pragma unroll
    for (int s = 1; s <= 2; s <<= 1) {
        s0 += __shfl_xor_sync(0xffffffffu, s0, s);
        s1 += __shfl_xor_sync(0xffffffffu, s1, s);
    }
    if (t == 0) {
        smf[OFF_RMP + r0 * 4 + kq] = m0;
        smf[OFF_RMP + r1 * 4 + kq] = m1;
        smf[OFF_RSP + r0 * 4 + kq] = s0;
        smf[OFF_RSP + r1 * 4 + kq] = s1;
    }

    // ================= P @ V: A regs, B = ldsm.trans(V) =================
    const int vky  = (lane & 7) + (((lane >> 3) & 1) << 3);
    const int vdim = (lane >> 4) << 3;
    float pa[4][4];
    #pragma unroll
    for (int nt = 0; nt < 4; nt++)
        #pragma unroll
        for (int e = 0; e < 4; e++) pa[nt][e] = 0.f;

    #pragma unroll
    for (int ks = 0; ks < 4; ks++) {
        const __half* vp = Vh + (kq * 64 + ks * 16 + vky) * 40;
        unsigned bv0[4], bv1[4];
        ldsm_x4t(bv0, vp + vdim);
        ldsm_x4t(bv1, vp + 16 + vdim);
        unsigned a0 = ah[2 * ks], a1 = bh[2 * ks], a2 = ah[2 * ks + 1], a3 = bh[2 * ks + 1];
        mma_f16(pa[0], a0, a1, a2, a3, bv0[0], bv0[1]);
        mma_f16(pa[1], a0, a1, a2, a3, bv0[2], bv0[3]);
        mma_f16(pa[2], a0, a1, a2, a3, bv1[0], bv1[1]);
        mma_f16(pa[3], a0, a1, a2, a3, bv1[2], bv1[3]);
    }

    // kq 1..3 store fp16 partials (relative to their local max)
    if (kq > 0) {
        uint4* red = (uint4*)(smf + OFF_RED) + ((kq - 1) * 4 + mt) * 64;
        red[lane]      = make_uint4(pack_h2(pa[0][0], pa[0][1]), pack_h2(pa[1][0], pa[1][1]),
                                    pack_h2(pa[2][0], pa[2][1]), pack_h2(pa[3][0], pa[3][1]));
        red[32 + lane] = make_uint4(pack_h2(pa[0][2], pa[0][3]), pack_h2(pa[1][2], pa[1][3]),
                                    pack_h2(pa[2][2], pa[2][3]), pack_h2(pa[3][2], pa[3][3]));
    }
    __syncthreads();   // (2) RED + RMP + RSP + LEP ready

    // ================= epilogue (kq == 0): rescale-combine =================
    if (kq == 0) {
        float4 mv0 = *(const float4*)(smf + OFF_RMP + r0 * 4);
        float4 mv1 = *(const float4*)(smf + OFF_RMP + r1 * 4);
        float4 sv0 = *(const float4*)(smf + OFF_RSP + r0 * 4);
        float4 sv1 = *(const float4*)(smf + OFF_RSP + r1 * 4);
        float mg0 = fmaxf(fmaxf(mv0.x, mv0.y), fmaxf(mv0.z, mv0.w));
        float mg1 = fmaxf(fmaxf(mv1.x, mv1.y), fmaxf(mv1.z, mv1.w));
        float c00 = ex2(mv0.x - mg0), c01 = ex2(mv0.y - mg0);
        float c02 = ex2(mv0.z - mg0), c03 = ex2(mv0.w - mg0);
        float c10 = ex2(mv1.x - mg1), c11 = ex2(mv1.y - mg1);
        float c12 = ex2(mv1.z - mg1), c13 = ex2(mv1.w - mg1);
        float den0 = sv0.x * c00 + sv0.y * c01 + sv0.z * c02 + sv0.w * c03;
        float den1 = sv1.x * c10 + sv1.y * c11 + sv1.z * c12 + sv1.w * c13;

        #pragma unroll
        for (int nt = 0; nt < 4; nt++) {
            pa[nt][0] *= c00; pa[nt][1] *= c00;
            pa[nt][2] *= c10; pa[nt][3] *= c10;
        }
        float sc0[3] = {c01, c02, c03};
        float sc1[3] = {c11, c12, c13};
        #pragma unroll
        for (int q = 0; q < 3; q++) {
            const uint4* red = (const uint4*)(smf + OFF_RED) + (q * 4 + mt) * 64;
            uint4 u0 = red[lane];
            uint4 u1 = red[32 + lane];
            const unsigned* p0 = (const unsigned*)&u0;
            const unsigned* p1 = (const unsigned*)&u1;
            #pragma unroll
            for (int nt = 0; nt < 4; nt++) {
                float2 f0 = __half22float2(*(const __half2*)&p0[nt]);
                float2 f1 = __half22float2(*(const __half2*)&p1[nt]);
                pa[nt][0] = fmaf(f0.x, sc0[q], pa[nt][0]);
                pa[nt][1] = fmaf(f0.y, sc0[q], pa[nt][1]);
                pa[nt][2] = fmaf(f1.x, sc1[q], pa[nt][2]);
                pa[nt][3] = fmaf(f1.y, sc1[q], pa[nt][3]);
            }
        }
        float inv0 = 1.0f / den0;
        float inv1 = 1.0f / den1;

        #pragma unroll
        for (int half = 0; half < 2; half++) {
            int row = half ? r1 : r0;
            if (row >= 49) continue;
            float inv = half ? inv1 : inv0;
            int qi = row / 7, qj = row - 7 * (row / 7);
            int pix = (ph * 7 + qi) * Wd + pw * 7 + qj;
            float* op = out + (size_t)b * plane + (size_t)pix * Cc + cbase;
            #pragma unroll
            for (int nt = 0; nt < 4; nt++) {
                int d0 = nt * 8 + 2 * t;
                float2 lep = *(const float2*)(smf + OFF_LEP + row * 32 + d0);
                float o0 = pa[nt][half * 2 + 0] * inv + lep.x;
                float o1 = pa[nt][half * 2 + 1] * inv + lep.y;
                *(float2*)(op + d0) = make_float2(o0, o1);
            }
        }
    }
}

extern "C" void kernel_launch(void* const* d_in, const int* in_sizes, int n_in,
                              void* d_out, int out_size)
{
    const float* qkv    = (const float*)d_in[0];
    const float* w_lepe = (const float*)d_in[1];
    const float* b_lepe = (const float*)d_in[2];
    float* out          = (float*)d_out;

    cudaFuncSetAttribute(lepe_attn_kernel,
                         cudaFuncAttributeMaxDynamicSharedMemorySize, SMEM_BYTES);
    lepe_attn_kernel<<<Bn * 8 * 8 * 4, 512, SMEM_BYTES>>>(qkv, w_lepe, b_lepe, out);
}